// round 1
// baseline (speedup 1.0000x reference)
#include <cuda_runtime.h>
#include <math.h>

// ---------------- problem constants ----------------
#define B_      1024
#define T_      256
#define DIN_    128
#define INTER_  269
#define CMD_    179
#define MOTOR_  64
#define OUT_    64
#define UNITS_  512
#define CAT0    (DIN_ + INTER_)   // 397
#define CAT1    (INTER_ + CMD_)   // 448
#define CAT2    (CMD_ + MOTOR_)   // 243

#define MB      8                 // batch rows per CTA
#define NBLK    (B_ / MB)         // 128 CTAs
#define NTHR    256

#define P0_ (CAT0 * INTER_)
#define P1_ (CAT1 * CMD_)
#define P2_ (CAT2 * MOTOR_)
#define PTOT_ (P0_ + P1_ + P2_)   // 202537 weight positions

// ---------------- device scratch (static, allowed) ----------------
__device__ __align__(16) float g_wt0[P0_ * 4];
__device__ __align__(16) float g_wt1[P1_ * 4];
__device__ __align__(16) float g_wt2[P2_ * 4];
__device__ int g_maskmode[3];

struct Params {
    const float* x;
    const float* hidden;
    const void*  mask0;
    const void*  mask1;
    const void*  mask2;
    const float* w0[4]; const float* b0[4];   // ff1, ff2, ta, tb
    const float* w1[4]; const float* b1[4];
    const float* w2[4]; const float* b2[4];
    const float* fc_w;  const float* fc_b;
    float* out;
};

// ---------------- mask dtype sniffing ----------------
// bool/uint8: ~84% of first 4096 bytes nonzero, all bytes <=1
// int32:      ~21% nonzero bytes, all bytes <=1
// float32:    bytes 0x80/0x3F present (>1)
__global__ void sniff_kernel(const void* m0, const void* m1, const void* m2) {
    int w = threadIdx.x >> 5, lane = threadIdx.x & 31;
    if (w >= 3) return;
    const unsigned char* p =
        (const unsigned char*)(w == 0 ? m0 : (w == 1 ? m1 : m2));
    int nz = 0, gt = 0;
    for (int i = lane; i < 4096; i += 32) {
        unsigned char v = p[i];
        nz += (v != 0);
        gt |= (v > 1);
    }
    nz = __reduce_add_sync(0xffffffffu, nz);
    gt = __reduce_or_sync(0xffffffffu, gt);
    if (lane == 0) g_maskmode[w] = gt ? 2 : (nz > 2048 ? 0 : 1);
}

__device__ __forceinline__ float mask_val(const void* mp, int mode, int e) {
    if (mode == 0) return ((const unsigned char*)mp)[e] ? 1.0f : 0.0f;
    if (mode == 1) return ((const int*)mp)[e] ? 1.0f : 0.0f;
    return (((const float*)mp)[e] != 0.0f) ? 1.0f : 0.0f;
}

// ---------------- weight prep: masked, transposed, gate-interleaved ----------------
// layout: wt[(k*NH + j)*4 + g], g = {ff1, ff2, ta, tb}; mask applies to g<2 only.
__global__ void prep_kernel(Params P) {
    int p = blockIdx.x * blockDim.x + threadIdx.x;
    if (p >= PTOT_) return;

    int NH, CATL, local, mode;
    float* wt;
    const float* const* ws;
    const void* mp;
    if (p < P0_) {
        local = p; NH = INTER_; CATL = CAT0; wt = g_wt0;
        ws = P.w0; mp = P.mask0; mode = g_maskmode[0];
    } else if (p < P0_ + P1_) {
        local = p - P0_; NH = CMD_; CATL = CAT1; wt = g_wt1;
        ws = P.w1; mp = P.mask1; mode = g_maskmode[1];
    } else {
        local = p - P0_ - P1_; NH = MOTOR_; CATL = CAT2; wt = g_wt2;
        ws = P.w2; mp = P.mask2; mode = g_maskmode[2];
    }
    int k = local / NH;
    int j = local - k * NH;
    int we = j * CATL + k;
    float m = mask_val(mp, mode, we);
    float4 v;
    v.x = ws[0][we] * m;
    v.y = ws[1][we] * m;
    v.z = ws[2][we];
    v.w = ws[3][we];
    *(float4*)(wt + (size_t)local * 4) = v;
}

// ---------------- per-layer forward (gates + combine) ----------------
template <int CATL, int NH>
__device__ __forceinline__ void layer_fw(const float* __restrict__ wt,
                                         const float* __restrict__ bias,
                                         const float* __restrict__ xc,
                                         float* __restrict__ gate,
                                         float* __restrict__ hout, int tid) {
    // gates: thread tau = (j, g). Weight loads coalesced 128B/warp; xc broadcast LDS.128
    for (int tau = tid; tau < NH * 4; tau += NTHR) {
        const float* w = wt + tau;           // (k*NH + j)*4 + g, k=0
        float a0 = 0, a1 = 0, a2 = 0, a3 = 0, a4 = 0, a5 = 0, a6 = 0, a7 = 0;
#pragma unroll 4
        for (int k = 0; k < CATL; ++k) {
            float wv = __ldg(w + (size_t)k * (NH * 4));
            float4 p0 = *(const float4*)(xc + k * MB);
            float4 p1 = *(const float4*)(xc + k * MB + 4);
            a0 += wv * p0.x; a1 += wv * p0.y; a2 += wv * p0.z; a3 += wv * p0.w;
            a4 += wv * p1.x; a5 += wv * p1.y; a6 += wv * p1.z; a7 += wv * p1.w;
        }
        int j = tau >> 2, g = tau & 3;
        float* gp = gate + g * (NH * MB) + j * MB;
        gp[0] = a0; gp[1] = a1; gp[2] = a2; gp[3] = a3;
        gp[4] = a4; gp[5] = a5; gp[6] = a6; gp[7] = a7;
    }
    __syncthreads();
    // combine: h = ff1 + sigmoid(z) * (ff2 - ff1)
    for (int tau = tid; tau < NH * MB; tau += NTHR) {
        int j = tau >> 3;
        float a0 = gate[tau];
        float a1 = gate[NH * MB + tau];
        float a2 = gate[2 * NH * MB + tau];
        float a3 = gate[3 * NH * MB + tau];
        float ff1 = tanhf(a0 + bias[j * 4 + 0]);
        float ff2 = tanhf(a1 + bias[j * 4 + 1]);
        float z = a2 + bias[j * 4 + 2] + a3 + bias[j * 4 + 3];
        float s = 1.0f / (1.0f + __expf(-z));
        hout[tau] = ff1 + s * (ff2 - ff1);
    }
    __syncthreads();
}

// ---------------- main persistent kernel: batch-parallel, no grid syncs ----------------
#define SMEM_FLOATS (CAT1*MB + INTER_*MB + CMD_*MB + MOTOR_*MB + 4*INTER_*MB \
                     + OUT_*MOTOR_ + OUT_ + INTER_*4 + CMD_*4 + MOTOR_*4)
#define SMEM_BYTES  (SMEM_FLOATS * 4)

__global__ void __launch_bounds__(NTHR) main_kernel(Params P) {
    extern __shared__ float sm[];
    float* xc    = sm;                          // 448*8
    float* h0    = xc + CAT1 * MB;              // 269*8
    float* h1    = h0 + INTER_ * MB;            // 179*8
    float* h2    = h1 + CMD_ * MB;              // 64*8
    float* gate  = h2 + MOTOR_ * MB;            // 4*269*8
    float* fcw   = gate + 4 * INTER_ * MB;      // 64*64 (transposed [m][o])
    float* fcb   = fcw + OUT_ * MOTOR_;         // 64
    float* bias0 = fcb + OUT_;                  // 269*4
    float* bias1 = bias0 + INTER_ * 4;          // 179*4
    float* bias2 = bias1 + CMD_ * 4;            // 64*4

    const int tid = threadIdx.x;
    const int b0 = blockIdx.x * MB;

    // one-time staging
    for (int q = tid; q < INTER_ * 4; q += NTHR) bias0[q] = P.b0[q & 3][q >> 2];
    for (int q = tid; q < CMD_ * 4; q += NTHR)   bias1[q] = P.b1[q & 3][q >> 2];
    for (int q = tid; q < MOTOR_ * 4; q += NTHR) bias2[q] = P.b2[q & 3][q >> 2];
    for (int q = tid; q < OUT_ * MOTOR_; q += NTHR) {
        int m = q >> 6, o = q & 63;
        fcw[m * OUT_ + o] = P.fc_w[o * MOTOR_ + m];
    }
    if (tid < OUT_) fcb[tid] = P.fc_b[tid];
    for (int q = tid; q < INTER_ * MB; q += NTHR) {
        int i = q >> 3, b = q & 7;
        h0[q] = P.hidden[(size_t)(b0 + b) * UNITS_ + i];
    }
    for (int q = tid; q < CMD_ * MB; q += NTHR) {
        int i = q >> 3, b = q & 7;
        h1[q] = P.hidden[(size_t)(b0 + b) * UNITS_ + INTER_ + i];
    }
    for (int q = tid; q < MOTOR_ * MB; q += NTHR) {
        int i = q >> 3, b = q & 7;
        h2[q] = P.hidden[(size_t)(b0 + b) * UNITS_ + INTER_ + CMD_ + i];
    }
    __syncthreads();

    for (int t = 0; t < T_; ++t) {
        // xc0 = [x_t, h0]   (k-major, batch innermost: xc[k*8 + b])
        {
            int lane = tid & 31, wb = tid >> 5;  // warp = batch row
            const float* xb = P.x + (size_t)(b0 + wb) * T_ * DIN_ + (size_t)t * DIN_;
#pragma unroll
            for (int kk = 0; kk < DIN_ / 32; ++kk) {
                int k = kk * 32 + lane;
                xc[k * MB + wb] = xb[k];
            }
        }
        for (int q = tid; q < INTER_ * MB; q += NTHR) xc[DIN_ * MB + q] = h0[q];
        __syncthreads();
        layer_fw<CAT0, INTER_>(g_wt0, bias0, xc, gate, h0, tid);

        // xc1 = [n0, h1_old]
        for (int q = tid; q < INTER_ * MB; q += NTHR) xc[q] = h0[q];
        for (int q = tid; q < CMD_ * MB; q += NTHR)   xc[INTER_ * MB + q] = h1[q];
        __syncthreads();
        layer_fw<CAT1, CMD_>(g_wt1, bias1, xc, gate, h1, tid);

        // xc2 = [n1, h2_old]
        for (int q = tid; q < CMD_ * MB; q += NTHR)   xc[q] = h1[q];
        for (int q = tid; q < MOTOR_ * MB; q += NTHR) xc[CMD_ * MB + q] = h2[q];
        __syncthreads();
        layer_fw<CAT2, MOTOR_>(g_wt2, bias2, xc, gate, h2, tid);

        // output head: pred[b][t][o] = fc_b[o] + sum_m n2[m,b] * fc_w[o][m]
        for (int q = tid; q < MB * OUT_; q += NTHR) {
            int b = q >> 6, o = q & 63;
            float acc = fcb[o];
#pragma unroll
            for (int m = 0; m < MOTOR_; ++m) acc += h2[m * MB + b] * fcw[m * OUT_ + o];
            P.out[(size_t)(b0 + b) * T_ * OUT_ + (size_t)t * OUT_ + o] = acc;
        }
        __syncthreads();
    }

    // final hidden state: hn = concat(h0, h1, h2), written after predictions block
    size_t hoff = (size_t)B_ * T_ * OUT_;
    for (int q = tid; q < INTER_ * MB; q += NTHR) {
        int i = q >> 3, b = q & 7;
        P.out[hoff + (size_t)(b0 + b) * UNITS_ + i] = h0[q];
    }
    for (int q = tid; q < CMD_ * MB; q += NTHR) {
        int i = q >> 3, b = q & 7;
        P.out[hoff + (size_t)(b0 + b) * UNITS_ + INTER_ + i] = h1[q];
    }
    for (int q = tid; q < MOTOR_ * MB; q += NTHR) {
        int i = q >> 3, b = q & 7;
        P.out[hoff + (size_t)(b0 + b) * UNITS_ + INTER_ + CMD_ + i] = h2[q];
    }
}

// ---------------- launch ----------------
extern "C" void kernel_launch(void* const* d_in, const int* in_sizes, int n_in,
                              void* d_out, int out_size) {
    (void)in_sizes; (void)n_in; (void)out_size;
    Params P;
    P.x      = (const float*)d_in[0];
    P.hidden = (const float*)d_in[1];
    P.mask0  = d_in[2];
    P.mask1  = d_in[3];
    P.mask2  = d_in[4];
    // per-layer: ff1_w, ff1_b, ff2_w, ff2_b, ta_w, ta_b, tb_w, tb_b
    const float** wp[3] = { P.w0, P.w1, P.w2 };
    const float** bp[3] = { P.b0, P.b1, P.b2 };
    int idx = 5;
    for (int l = 0; l < 3; ++l) {
        for (int g = 0; g < 4; ++g) {
            wp[l][g] = (const float*)d_in[idx++];
            bp[l][g] = (const float*)d_in[idx++];
        }
    }
    P.fc_w = (const float*)d_in[idx++];
    P.fc_b = (const float*)d_in[idx++];
    P.out  = (float*)d_out;

    cudaFuncSetAttribute(main_kernel, cudaFuncAttributeMaxDynamicSharedMemorySize,
                         SMEM_BYTES);

    sniff_kernel<<<1, 96>>>(P.mask0, P.mask1, P.mask2);
    prep_kernel<<<(PTOT_ + 255) / 256, 256>>>(P);
    main_kernel<<<NBLK, NTHR, SMEM_BYTES>>>(P);
}

// round 2
// speedup vs baseline: 2.3958x; 2.3958x over previous
#include <cuda_runtime.h>
#include <math.h>

// ---------------- problem constants ----------------
#define B_      1024
#define T_      256
#define DIN_    128
#define INTER_  269
#define CMD_    179
#define MOTOR_  64
#define OUT_    64
#define UNITS_  512
#define CAT0    (DIN_ + INTER_)   // 397
#define CAT1    (INTER_ + CMD_)   // 448
#define CAT2    (CMD_ + MOTOR_)   // 243

#define MB      8                 // batch rows per CTA
#define NBLK    (B_ / MB)         // 128 CTAs
#define NTHR    512

#define KC0     3                 // k-split per layer
#define KC1     5
#define KC2     8
#define TASKS0  (INTER_ * KC0)    // 807
#define TASKS1  (CMD_ * KC1)      // 895
#define TASKS2  (MOTOR_ * KC2)    // 512
#define PSTRIDE 40                // floats per task slot (conflict-free combine)
#define MAXTASK TASKS1            // 895

#define P0_ (CAT0 * INTER_)
#define P1_ (CAT1 * CMD_)
#define P2_ (CAT2 * MOTOR_)
#define PTOT_ (P0_ + P1_ + P2_)

// ---------------- device scratch (static, allowed) ----------------
__device__ __align__(16) float g_wt0[P0_ * 4];
__device__ __align__(16) float g_wt1[P1_ * 4];
__device__ __align__(16) float g_wt2[P2_ * 4];
__device__ int g_maskmode[3];

struct Params {
    const float* x;
    const float* hidden;
    const void*  mask0;
    const void*  mask1;
    const void*  mask2;
    const float* w0[4]; const float* b0[4];   // ff1, ff2, ta, tb
    const float* w1[4]; const float* b1[4];
    const float* w2[4]; const float* b2[4];
    const float* fc_w;  const float* fc_b;
    float* out;
};

// ---------------- mask dtype sniffing ----------------
__global__ void sniff_kernel(const void* m0, const void* m1, const void* m2) {
    int w = threadIdx.x >> 5, lane = threadIdx.x & 31;
    if (w >= 3) return;
    const unsigned char* p =
        (const unsigned char*)(w == 0 ? m0 : (w == 1 ? m1 : m2));
    int nz = 0, gt = 0;
    for (int i = lane; i < 4096; i += 32) {
        unsigned char v = p[i];
        nz += (v != 0);
        gt |= (v > 1);
    }
    nz = __reduce_add_sync(0xffffffffu, nz);
    gt = __reduce_or_sync(0xffffffffu, gt);
    if (lane == 0) g_maskmode[w] = gt ? 2 : (nz > 2048 ? 0 : 1);
}

__device__ __forceinline__ float mask_val(const void* mp, int mode, int e) {
    if (mode == 0) return ((const unsigned char*)mp)[e] ? 1.0f : 0.0f;
    if (mode == 1) return ((const int*)mp)[e] ? 1.0f : 0.0f;
    return (((const float*)mp)[e] != 0.0f) ? 1.0f : 0.0f;
}

// ---------------- weight prep: masked, transposed, gate-interleaved float4 ----------------
// layout: wt[k*NH + j] = float4{ff1, ff2, ta, tb}, mask on ff1/ff2 only.
__global__ void prep_kernel(Params P) {
    int p = blockIdx.x * blockDim.x + threadIdx.x;
    if (p >= PTOT_) return;

    int NH, CATL, local, mode;
    float* wt;
    const float* const* ws;
    const void* mp;
    if (p < P0_) {
        local = p; NH = INTER_; CATL = CAT0; wt = g_wt0;
        ws = P.w0; mp = P.mask0; mode = g_maskmode[0];
    } else if (p < P0_ + P1_) {
        local = p - P0_; NH = CMD_; CATL = CAT1; wt = g_wt1;
        ws = P.w1; mp = P.mask1; mode = g_maskmode[1];
    } else {
        local = p - P0_ - P1_; NH = MOTOR_; CATL = CAT2; wt = g_wt2;
        ws = P.w2; mp = P.mask2; mode = g_maskmode[2];
    }
    int k = local / NH;
    int j = local - k * NH;
    int we = j * CATL + k;
    float m = mask_val(mp, mode, we);
    float4 v;
    v.x = ws[0][we] * m;
    v.y = ws[1][we] * m;
    v.z = ws[2][we];
    v.w = ws[3][we];
    *(float4*)(wt + (size_t)local * 4) = v;
}

// ---------------- packed f32x2 helpers ----------------
__device__ __forceinline__ unsigned long long pack2(float w) {
    unsigned long long r;
    asm("mov.b64 %0, {%1, %1};" : "=l"(r) : "f"(w));
    return r;
}
#define FFMA2(acc, w2, x2) \
    asm("fma.rn.f32x2 %0, %1, %2, %0;" : "+l"(acc) : "l"(w2), "l"(x2))

// ---------------- per-layer forward: k-split gates + combine ----------------
template <int CATL, int NH, int KC>
__device__ __forceinline__ void layer_fw(const float4* __restrict__ wt,
                                         const float* __restrict__ bias,
                                         const float* __restrict__ xc,
                                         float* __restrict__ part,
                                         float* __restrict__ hout, int tid) {
    const int TASKS = NH * KC;
    for (int task = tid; task < TASKS; task += NTHR) {
        int kc = task / NH;
        int j  = task - kc * NH;
        int k0 = (CATL * kc) / KC;
        int k1 = (CATL * (kc + 1)) / KC;
        const float4* w = wt + (size_t)k0 * NH + j;
        unsigned long long a[16];
#pragma unroll
        for (int i = 0; i < 16; ++i) a[i] = 0ULL;

#pragma unroll 2
        for (int k = k0; k < k1; ++k, w += NH) {
            float4 wv = __ldg(w);
            unsigned long long wA = pack2(wv.x);
            unsigned long long wB = pack2(wv.y);
            unsigned long long wC = pack2(wv.z);
            unsigned long long wD = pack2(wv.w);
            const ulonglong2* xp = (const ulonglong2*)(xc + k * MB);
            ulonglong2 xlo = xp[0];   // (b0,b1),(b2,b3)
            ulonglong2 xhi = xp[1];   // (b4,b5),(b6,b7)
            FFMA2(a[0],  wA, xlo.x); FFMA2(a[1],  wA, xlo.y);
            FFMA2(a[2],  wA, xhi.x); FFMA2(a[3],  wA, xhi.y);
            FFMA2(a[4],  wB, xlo.x); FFMA2(a[5],  wB, xlo.y);
            FFMA2(a[6],  wB, xhi.x); FFMA2(a[7],  wB, xhi.y);
            FFMA2(a[8],  wC, xlo.x); FFMA2(a[9],  wC, xlo.y);
            FFMA2(a[10], wC, xhi.x); FFMA2(a[11], wC, xhi.y);
            FFMA2(a[12], wD, xlo.x); FFMA2(a[13], wD, xlo.y);
            FFMA2(a[14], wD, xhi.x); FFMA2(a[15], wD, xhi.y);
        }
        float* pp = part + task * PSTRIDE;
#pragma unroll
        for (int g = 0; g < 4; ++g) {
            ulonglong2 s0; s0.x = a[g * 4 + 0]; s0.y = a[g * 4 + 1];
            ulonglong2 s1; s1.x = a[g * 4 + 2]; s1.y = a[g * 4 + 3];
            *(ulonglong2*)(pp + g * 8)     = s0;
            *(ulonglong2*)(pp + g * 8 + 4) = s1;
        }
    }
    __syncthreads();
    // combine over KC partials + activations
    for (int it = tid; it < NH * MB; it += NTHR) {
        int j = it >> 3, b = it & 7;
        float s0 = 0.f, s1 = 0.f, s2 = 0.f, s3 = 0.f;
#pragma unroll
        for (int kc = 0; kc < KC; ++kc) {
            const float* pp = part + (kc * NH + j) * PSTRIDE + b;
            s0 += pp[0]; s1 += pp[8]; s2 += pp[16]; s3 += pp[24];
        }
        float ff1 = tanhf(s0 + bias[j * 4 + 0]);
        float ff2 = tanhf(s1 + bias[j * 4 + 1]);
        float z = s2 + bias[j * 4 + 2] + s3 + bias[j * 4 + 3];
        float s = 1.0f / (1.0f + __expf(-z));
        hout[it] = ff1 + s * (ff2 - ff1);
    }
    __syncthreads();
}

// ---------------- main persistent kernel ----------------
#define SMEM_FLOATS (MAXTASK*PSTRIDE + CAT1*MB + INTER_*MB + CMD_*MB + MOTOR_*MB \
                     + OUT_*MOTOR_ + OUT_ + INTER_*4 + CMD_*4 + MOTOR_*4)
#define SMEM_BYTES  (SMEM_FLOATS * 4)

__global__ void __launch_bounds__(NTHR) main_kernel(Params P) {
    extern __shared__ float sm[];
    float* part  = sm;                          // 895*40
    float* xc    = part + MAXTASK * PSTRIDE;    // 448*8
    float* h0    = xc + CAT1 * MB;              // 269*8
    float* h1    = h0 + INTER_ * MB;            // 179*8
    float* h2    = h1 + CMD_ * MB;              // 64*8
    float* fcw   = h2 + MOTOR_ * MB;            // 64*64 ([m][o])
    float* fcb   = fcw + OUT_ * MOTOR_;         // 64
    float* bias0 = fcb + OUT_;                  // 269*4
    float* bias1 = bias0 + INTER_ * 4;          // 179*4
    float* bias2 = bias1 + CMD_ * 4;            // 64*4

    const int tid = threadIdx.x;
    const int b0 = blockIdx.x * MB;

    // one-time staging
    for (int q = tid; q < INTER_ * 4; q += NTHR) bias0[q] = P.b0[q & 3][q >> 2];
    for (int q = tid; q < CMD_ * 4; q += NTHR)   bias1[q] = P.b1[q & 3][q >> 2];
    for (int q = tid; q < MOTOR_ * 4; q += NTHR) bias2[q] = P.b2[q & 3][q >> 2];
    for (int q = tid; q < OUT_ * MOTOR_; q += NTHR) {
        int m = q >> 6, o = q & 63;
        fcw[m * OUT_ + o] = P.fc_w[o * MOTOR_ + m];
    }
    if (tid < OUT_) fcb[tid] = P.fc_b[tid];
    for (int q = tid; q < INTER_ * MB; q += NTHR) {
        int i = q >> 3, b = q & 7;
        h0[q] = P.hidden[(size_t)(b0 + b) * UNITS_ + i];
    }
    for (int q = tid; q < CMD_ * MB; q += NTHR) {
        int i = q >> 3, b = q & 7;
        h1[q] = P.hidden[(size_t)(b0 + b) * UNITS_ + INTER_ + i];
    }
    for (int q = tid; q < MOTOR_ * MB; q += NTHR) {
        int i = q >> 3, b = q & 7;
        h2[q] = P.hidden[(size_t)(b0 + b) * UNITS_ + INTER_ + CMD_ + i];
    }
    __syncthreads();

    for (int t = 0; t < T_; ++t) {
        // xc0 = [x_t, h0]   (k-major, batch innermost: xc[k*8 + b])
        {
            int w = tid >> 5, lane = tid & 31;
            int row = w & 7, half = w >> 3;       // 16 warps: 8 rows x 2 halves
            const float* xb = P.x + ((size_t)(b0 + row) * T_ + t) * DIN_ + half * 64;
#pragma unroll
            for (int kk = 0; kk < 2; ++kk) {
                int k = half * 64 + kk * 32 + lane;
                xc[k * MB + row] = xb[kk * 32 + lane];
            }
        }
        for (int q = tid; q < INTER_ * MB; q += NTHR) xc[DIN_ * MB + q] = h0[q];
        __syncthreads();
        layer_fw<CAT0, INTER_, KC0>((const float4*)g_wt0, bias0, xc, part, h0, tid);

        // xc1 = [n0, h1_old]
        for (int q = tid; q < INTER_ * MB; q += NTHR) xc[q] = h0[q];
        for (int q = tid; q < CMD_ * MB; q += NTHR)   xc[INTER_ * MB + q] = h1[q];
        __syncthreads();
        layer_fw<CAT1, CMD_, KC1>((const float4*)g_wt1, bias1, xc, part, h1, tid);

        // xc2 = [n1, h2_old]
        for (int q = tid; q < CMD_ * MB; q += NTHR)   xc[q] = h1[q];
        for (int q = tid; q < MOTOR_ * MB; q += NTHR) xc[CMD_ * MB + q] = h2[q];
        __syncthreads();
        layer_fw<CAT2, MOTOR_, KC2>((const float4*)g_wt2, bias2, xc, part, h2, tid);

        // output head: pred[b][t][o] = fc_b[o] + sum_m n2[m,b] * fc_w[m][o]
        for (int q = tid; q < MB * OUT_; q += NTHR) {
            int b = q >> 6, o = q & 63;
            float acc = fcb[o];
#pragma unroll
            for (int m = 0; m < MOTOR_; ++m) acc += h2[m * MB + b] * fcw[m * OUT_ + o];
            P.out[(size_t)(b0 + b) * T_ * OUT_ + (size_t)t * OUT_ + o] = acc;
        }
        __syncthreads();
    }

    // final hidden state: hn = concat(h0, h1, h2) after predictions block
    size_t hoff = (size_t)B_ * T_ * OUT_;
    for (int q = tid; q < INTER_ * MB; q += NTHR) {
        int i = q >> 3, b = q & 7;
        P.out[hoff + (size_t)(b0 + b) * UNITS_ + i] = h0[q];
    }
    for (int q = tid; q < CMD_ * MB; q += NTHR) {
        int i = q >> 3, b = q & 7;
        P.out[hoff + (size_t)(b0 + b) * UNITS_ + INTER_ + i] = h1[q];
    }
    for (int q = tid; q < MOTOR_ * MB; q += NTHR) {
        int i = q >> 3, b = q & 7;
        P.out[hoff + (size_t)(b0 + b) * UNITS_ + INTER_ + CMD_ + i] = h2[q];
    }
}

// ---------------- launch ----------------
extern "C" void kernel_launch(void* const* d_in, const int* in_sizes, int n_in,
                              void* d_out, int out_size) {
    (void)in_sizes; (void)n_in; (void)out_size;
    Params P;
    P.x      = (const float*)d_in[0];
    P.hidden = (const float*)d_in[1];
    P.mask0  = d_in[2];
    P.mask1  = d_in[3];
    P.mask2  = d_in[4];
    const float** wp[3] = { P.w0, P.w1, P.w2 };
    const float** bp[3] = { P.b0, P.b1, P.b2 };
    int idx = 5;
    for (int l = 0; l < 3; ++l) {
        for (int g = 0; g < 4; ++g) {
            wp[l][g] = (const float*)d_in[idx++];
            bp[l][g] = (const float*)d_in[idx++];
        }
    }
    P.fc_w = (const float*)d_in[idx++];
    P.fc_b = (const float*)d_in[idx++];
    P.out  = (float*)d_out;

    cudaFuncSetAttribute(main_kernel, cudaFuncAttributeMaxDynamicSharedMemorySize,
                         SMEM_BYTES);

    sniff_kernel<<<1, 96>>>(P.mask0, P.mask1, P.mask2);
    prep_kernel<<<(PTOT_ + 255) / 256, 256>>>(P);
    main_kernel<<<NBLK, NTHR, SMEM_BYTES>>>(P);
}